// round 4
// baseline (speedup 1.0000x reference)
#include <cuda_runtime.h>
#include <cstdint>
#include <cstddef>

#define NBLK   32
#define LANES  32
#define W      2048
#define H      2048
#define WSK_PAD 4096            // 4095 real columns, padded to 4096 (col 4095 unused)
#define CH     8
#define NCHUNK (WSK_PAD / CH)   // 512
#define FC_IN  1024
#define FC_OUT 10
#define NFLAT  ((H * W) / FC_IN) // 4096

// ---- scratch (device globals: no runtime allocation allowed) ----
__device__ float g_unskew[(size_t)H * W];        // 16 MB activations, row-major [r][c]
__device__ float g_bound[NBLK][WSK_PAD];         // boundary row value per column per block
__device__ int   g_progress[NBLK];               // columns completed by each block

// ---- accurate-enough tanh: (e-1)*rcp(e+1), e = 2^(z*2*log2 e). abs err ~1e-7 ----
__device__ __forceinline__ float fast_tanh(float z) {
    float zc = fminf(z, 10.0f);                  // avoid inf*0 NaN; tanh(10)=1-4e-9
    float t = zc * 2.8853900817779268f;          // 2*log2(e)
    float e;
    asm("ex2.approx.f32 %0, %1;" : "=f"(e) : "f"(t));
    float num = e - 1.0f;
    float den = e + 1.0f;
    float r;
    asm("rcp.approx.f32 %0, %1;" : "=f"(r) : "f"(den));
    return num * r;
}

__device__ __forceinline__ int acq_load(const int* p) {
    int v;
    asm volatile("ld.acquire.gpu.global.s32 %0, [%1];" : "=r"(v) : "l"(p) : "memory");
    return v;
}
__device__ __forceinline__ void rel_store(int* p, int v) {
    asm volatile("st.release.gpu.global.s32 [%0], %1;" :: "l"(p), "r"(v) : "memory");
}
// L2-only load: immune to stale L1 lines for producer-written boundary values
__device__ __forceinline__ float ldcg(const float* p) {
    float v;
    asm volatile("ld.global.cg.f32 %0, [%1];" : "=f"(v) : "l"(p));
    return v;
}

__global__ void init_kernel() {
    if (threadIdx.x < NBLK) g_progress[threadIdx.x] = 0;
}

// Load CH image values of row r for columns [c0, c0+CH); out-of-band -> 0
// (inp = fma(w, val, cb) then gives exactly cb outside the band, matching reference)
__device__ __forceinline__ void load_chunk(const float* __restrict__ row, int c0, int r,
                                           float* buf) {
#pragma unroll
    for (int cc = 0; cc < CH; cc++) {
        int cl = c0 + cc - r;
        float v = 0.0f;
        if ((unsigned)cl < (unsigned)W) v = row[cl];
        buf[cc] = v;
    }
}

// One warp per block. Lane l owns rows r0=base+2l, r1=r0+1.
// h_new[r] = tanh(k0*h_old[r-1] + k1*h_old[r] + cin[r][j]) over 4096 columns.
// Block b lags block b-1; boundary (row base-1) values flow via g_bound/g_progress.
__global__ void __launch_bounds__(LANES, 1) scan_kernel(
    const float* __restrict__ img, const float* __restrict__ w_in,
    const float* __restrict__ b_in, const float* __restrict__ w_state,
    const float* __restrict__ b_state)
{
    const int b    = blockIdx.x;
    const int lane = threadIdx.x;
    const float w  = w_in[0];
    const float k0 = w_state[0];
    const float k1 = w_state[1];
    const float cb = b_in[0] + b_state[0];

    const int r0 = b * (H / NBLK) + 2 * lane;
    const int r1 = r0 + 1;
    const float* row0 = img + (size_t)r0 * W;
    const float* row1 = img + (size_t)r1 * W;
    float* u0 = g_unskew + (size_t)r0 * W;
    float* u1 = g_unskew + (size_t)r1 * W;

    const bool producer = (b < NBLK - 1) && (lane == LANES - 1);
    const float* ub = (b > 0) ? g_bound[b - 1] : g_bound[0];

    float h0 = 0.0f, h1 = 0.0f;
    float bcur = 0.0f, bnext = 0.0f;   // boundary vals: lane l holds index c0-1+l
    int kn = 0;                        // cached upstream progress

    // double-buffered image inputs (distance-1 chunk prefetch)
    float icur0[CH], icur1[CH], inxt0[CH], inxt1[CH];
    load_chunk(row0, 0, r0, icur0);
    load_chunk(row1, 0, r1, icur1);
    load_chunk(row0, CH, r0, inxt0);
    load_chunk(row1, CH, r1, inxt1);

    if (b > 0) {
        while (kn < CH - 1) kn = acq_load(&g_progress[b - 1]);
        {
            int idx = lane - 1;        // chunk 0 needs indices -1..CH-2 (idx -1 -> h=0)
            bcur = (lane < CH && idx >= 0) ? ldcg(ub + idx) : 0.0f;
        }
        while (kn < 2 * CH - 1) kn = acq_load(&g_progress[b - 1]);
        bnext = (lane < CH) ? ldcg(ub + (CH - 1 + lane)) : 0.0f;
        kn = acq_load(&g_progress[b - 1]);   // prefetch for the loop
    }

    for (int n = 0; n < NCHUNK; n++) {
        const int c0 = n * CH;
#pragma unroll
        for (int cc = 0; cc < CH; cc++) {
            const int j = c0 + cc;
            float bv  = __shfl_sync(0xffffffffu, bcur, cc);   // boundary val for col j-1
            float upw = __shfl_up_sync(0xffffffffu, h1, 1);   // neighbor lane's row r0-1
            float up  = (lane == 0) ? bv : upw;
            float cin0 = fmaf(w, icur0[cc], cb);
            float cin1 = fmaf(w, icur1[cc], cb);
            float z0 = fmaf(k0, up, fmaf(k1, h0, cin0));
            float z1 = fmaf(k0, h0, fmaf(k1, h1, cin1));      // uses OLD h0
            float a0 = fast_tanh(z0);
            float a1 = fast_tanh(z1);
            h0 = a0; h1 = a1;
            int cl0 = j - r0;
            int cl1 = j - r1;
            if ((unsigned)cl0 < (unsigned)W) u0[cl0] = a0;
            if ((unsigned)cl1 < (unsigned)W) u1[cl1] = a1;
            if (producer) g_bound[b][j] = a1;                 // block's last row
        }
        if (producer) rel_store(&g_progress[b], c0 + CH);     // publish chunk

        // rotate + prefetch image inputs for chunk n+2
#pragma unroll
        for (int cc = 0; cc < CH; cc++) { icur0[cc] = inxt0[cc]; icur1[cc] = inxt1[cc]; }
        if (n + 2 < NCHUNK) {
            load_chunk(row0, c0 + 2 * CH, r0, inxt0);
            load_chunk(row1, c0 + 2 * CH, r1, inxt1);
        }
        // rotate + prefetch boundary values for chunk n+2 (distance-2: latency hidden)
        bcur = bnext;
        if (b > 0 && n + 2 < NCHUNK) {
            int need = (n + 2) * CH + (CH - 1);
            while (kn < need) kn = acq_load(&g_progress[b - 1]);
            bnext = (lane < CH) ? ldcg(ub + ((n + 2) * CH - 1 + lane)) : 0.0f;
            kn = acq_load(&g_progress[b - 1]);                // refresh for next check
        }
    }
}

// out[f][o] = sum_k unskew_flat[f][k] * fc_w[o][k] + fc_b[o]; 10 warps, one per output
__global__ void fc_kernel(const float* __restrict__ fc_w, const float* __restrict__ fc_b,
                          float* __restrict__ out) {
    __shared__ float sact[FC_IN];
    const int f = blockIdx.x;
    const float* src = g_unskew + (size_t)f * FC_IN;
    for (int k = threadIdx.x; k < FC_IN; k += blockDim.x) sact[k] = src[k];
    __syncthreads();
    const int wid = threadIdx.x >> 5;
    const int lane = threadIdx.x & 31;
    if (wid < FC_OUT) {
        const float* wr = fc_w + wid * FC_IN;
        float acc = 0.0f;
#pragma unroll 8
        for (int k = lane; k < FC_IN; k += 32) acc = fmaf(sact[k], wr[k], acc);
#pragma unroll
        for (int s = 16; s > 0; s >>= 1) acc += __shfl_down_sync(0xffffffffu, acc, s);
        if (lane == 0) out[f * FC_OUT + wid] = acc + fc_b[wid];
    }
}

extern "C" void kernel_launch(void* const* d_in, const int* in_sizes, int n_in,
                              void* d_out, int out_size) {
    const float* x       = (const float*)d_in[0];
    const float* w_in    = (const float*)d_in[1];
    const float* b_in    = (const float*)d_in[2];
    const float* w_state = (const float*)d_in[3];
    const float* b_state = (const float*)d_in[4];
    const float* fc_w    = (const float*)d_in[5];
    const float* fc_b    = (const float*)d_in[6];
    (void)in_sizes; (void)n_in; (void)out_size;

    init_kernel<<<1, 32>>>();                              // reset pipeline flags per replay
    scan_kernel<<<NBLK, LANES>>>(x, w_in, b_in, w_state, b_state);
    fc_kernel<<<NFLAT, 320>>>(fc_w, fc_b, (float*)d_out);
}

// round 6
// speedup vs baseline: 1.1025x; 1.1025x over previous
#include <cuda_runtime.h>
#include <cstdint>
#include <cstddef>

#define NBLK   32
#define RPB    64               // rows per block
#define W      2048
#define H      2048
#define WSK    4096             // 4095 real skewed columns, padded to 4096
#define CH     8
#define NCHUNK (WSK / CH)       // 512
#define FC_IN  1024
#define FC_OUT 10
#define NFLAT  ((H * W) / FC_IN) // 4096

// ---- scratch (device globals: no runtime allocation allowed) ----
__device__ float g_unskew[(size_t)H * W];     // unskewed activations, row-major [r][c]
__device__ float g_bound[NBLK][WSK];          // last-row value per column per block
__device__ int   g_progress[NBLK];            // columns published by each block

// ---- accurate tanh: (e-1)*rcp(e+1), e = 2^(min(z,10)*2*log2 e). abs err ~1e-7 ----
__device__ __forceinline__ float fast_tanh(float z) {
    float zc = fminf(z, 10.0f);
    float t = zc * 2.8853900817779268f;
    float e;
    asm("ex2.approx.f32 %0, %1;" : "=f"(e) : "f"(t));
    float num = e - 1.0f;
    float den = e + 1.0f;
    float r;
    asm("rcp.approx.f32 %0, %1;" : "=f"(r) : "f"(den));
    return num * r;
}

__device__ __forceinline__ int acq_load(const int* p) {
    int v;
    asm volatile("ld.acquire.gpu.global.s32 %0, [%1];" : "=r"(v) : "l"(p) : "memory");
    return v;
}
__device__ __forceinline__ void rel_store(int* p, int v) {
    asm volatile("st.release.gpu.global.s32 [%0], %1;" :: "l"(p), "r"(v) : "memory");
}
// L2-only load: immune to stale L1 lines for producer-written boundary values
__device__ __forceinline__ float ldcg(const float* p) {
    float v;
    asm volatile("ld.global.cg.f32 %0, [%1];" : "=f"(v) : "l"(p));
    return v;
}

__global__ void init_kernel() {
    if (threadIdx.x < NBLK) g_progress[threadIdx.x] = 0;
}

// 2 warps per block. Warp 0: compute only (lane l owns rows base+l, base+32+l).
// Warp 1: all global memory traffic, coalesced, staged through shared tiles.
__global__ void __launch_bounds__(64, 1) scan_kernel(
    const float* __restrict__ img, const float* __restrict__ w_in,
    const float* __restrict__ b_in, const float* __restrict__ w_state,
    const float* __restrict__ b_state)
{
    __shared__ float s_img[3][RPB][CH];   // image tiles (chunk n in buf n%3)
    __shared__ float s_act[2][RPB][CH];   // activation tiles (chunk n in buf n&1)
    __shared__ float s_bnd[3][CH];        // boundary vals (chunk n in buf n%3)

    const int b    = blockIdx.x;
    const int tid  = threadIdx.x;
    const int lane = tid & 31;
    const int base = b * RPB;

    if (tid < 32) {
        // ================= compute warp =================
        const float w  = w_in[0];
        const float k0 = w_state[0];
        const float k1 = w_state[1];
        const float cb = b_in[0] + b_state[0];
        float hA = 0.0f, hB = 0.0f;       // rows base+lane, base+32+lane

        for (int n = 0; n < NCHUNK; n++) {
            __syncthreads();              // img/bnd for chunk n ready; act[n&1] free
            const int ib = n % 3;
            float4 iA0 = *(const float4*)&s_img[ib][lane][0];
            float4 iA1 = *(const float4*)&s_img[ib][lane][4];
            float4 iB0 = *(const float4*)&s_img[ib][32 + lane][0];
            float4 iB1 = *(const float4*)&s_img[ib][32 + lane][4];
            float bcur = s_bnd[ib][lane & 7];    // lane k<8 holds bound idx n*8-1+k
            float iA[8] = {iA0.x, iA0.y, iA0.z, iA0.w, iA1.x, iA1.y, iA1.z, iA1.w};
            float iB[8] = {iB0.x, iB0.y, iB0.z, iB0.w, iB1.x, iB1.y, iB1.z, iB1.w};
            float aA[8], aB[8];
#pragma unroll
            for (int cc = 0; cc < CH; cc++) {
                float bv    = __shfl_sync(0xffffffffu, bcur, cc);  // bound for col j-1
                float upA_w = __shfl_up_sync(0xffffffffu, hA, 1);
                float upB_w = __shfl_up_sync(0xffffffffu, hB, 1);
                float wrapA = __shfl_sync(0xffffffffu, hA, 31);    // row base+31 (old)
                float upA = (lane == 0) ? bv    : upA_w;
                float upB = (lane == 0) ? wrapA : upB_w;
                float zA = fmaf(k0, upA, fmaf(k1, hA, fmaf(w, iA[cc], cb)));
                float zB = fmaf(k0, upB, fmaf(k1, hB, fmaf(w, iB[cc], cb)));
                hA = fast_tanh(zA);
                hB = fast_tanh(zB);
                aA[cc] = hA; aB[cc] = hB;
            }
            const int ab = n & 1;
            *(float4*)&s_act[ab][lane][0]      = make_float4(aA[0], aA[1], aA[2], aA[3]);
            *(float4*)&s_act[ab][lane][4]      = make_float4(aA[4], aA[5], aA[6], aA[7]);
            *(float4*)&s_act[ab][32 + lane][0] = make_float4(aB[0], aB[1], aB[2], aB[3]);
            *(float4*)&s_act[ab][32 + lane][4] = make_float4(aB[4], aB[5], aB[6], aB[7]);
        }
        __syncthreads();                  // final: hand last tile to warp 1
    } else {
        // ================= memory warp =================
        const int fr = lane >> 3;         // 0..3 : row sub-index
        const int fc = lane & 7;          // 0..7 : column within chunk
        int Bidx[16], off[16];            // per-it constants; chunk m addr = Bidx+8m
#pragma unroll
        for (int it = 0; it < 16; it++) {
            int g_row = base + it * 4 + fr;
            off[it]  = fc - g_row;                 // col = 8*m + off
            Bidx[it] = g_row * (W - 1) + fc;       // addr = Bidx + 8*m
        }
        const float* ub = (b > 0) ? g_bound[b - 1] : g_bound[0];
        const bool prod = (b < NBLK - 1);
        int kn = 0;

        if (lane < 8) { s_bnd[0][lane] = 0.f; s_bnd[1][lane] = 0.f; s_bnd[2][lane] = 0.f; }

        // prologue: img chunks 0,1 -> smem; chunk 2 -> regs
        float rimg[16];
#pragma unroll
        for (int it = 0; it < 16; it++) {
            int row = it * 4 + fr;
            { int col = off[it];      s_img[0][row][fc] = ((unsigned)col < W) ? img[Bidx[it]]      : 0.f; }
            { int col = 8 + off[it];  s_img[1][row][fc] = ((unsigned)col < W) ? img[Bidx[it] + 8]  : 0.f; }
            { int col = 16 + off[it]; rimg[it]          = ((unsigned)col < W) ? img[Bidx[it] + 16] : 0.f; }
        }
        float rbnd = 0.0f;
        if (b > 0) {                       // boundary chunks 0,1 -> smem; 2 -> reg
            while (kn < 7)  kn = acq_load(&g_progress[b - 1]);
            if (lane < 8) { int idx = lane - 1; s_bnd[0][lane] = (idx >= 0) ? ldcg(ub + idx) : 0.f; }
            while (kn < 15) kn = acq_load(&g_progress[b - 1]);
            if (lane < 8) s_bnd[1][lane] = ldcg(ub + 7 + lane);
            while (kn < 23) kn = acq_load(&g_progress[b - 1]);
            if (lane < 8) rbnd = ldcg(ub + 15 + lane);
        }

        for (int n = 0; n < NCHUNK; n++) {
            __syncthreads();
            const int m2 = n + 2, m3 = n + 3;
            // publish staged chunk n+2 (img + bnd) into smem
            if (m2 < NCHUNK) {
                const int bi = m2 % 3;
#pragma unroll
                for (int it = 0; it < 16; it++) s_img[bi][it * 4 + fr][fc] = rimg[it];
                if (b > 0 && lane < 8) s_bnd[bi][lane] = rbnd;
            }
            // issue loads for chunk n+3 (consumed next window: full latency slack)
            if (m3 < NCHUNK) {
                const int a = m3 * 8;
#pragma unroll
                for (int it = 0; it < 16; it++) {
                    int col = a + off[it];
                    rimg[it] = ((unsigned)col < W) ? img[Bidx[it] + a] : 0.f;
                }
            }
            // flush activation tile of chunk n-1 (coalesced) + publish boundary
            if (n >= 1) {
                const int fb = (n - 1) & 1;
                const int a  = (n - 1) * 8;
#pragma unroll
                for (int it = 0; it < 16; it++) {
                    float v = s_act[fb][it * 4 + fr][fc];
                    int col = a + off[it];
                    if ((unsigned)col < W) g_unskew[Bidx[it] + a] = v;
                }
                if (prod) {
                    if (lane < 8) g_bound[b][a + lane] = s_act[fb][RPB - 1][lane];
                    __threadfence();
                    __syncwarp();
                    if (lane == 0) rel_store(&g_progress[b], n * 8);
                }
            }
            // fetch boundary chunk n+3 into reg (usually zero polls: kn caches)
            if (b > 0 && m3 < NCHUNK) {
                const int need = m3 * 8 + 7;
                while (kn < need) kn = acq_load(&g_progress[b - 1]);
                if (lane < 8) rbnd = ldcg(ub + m3 * 8 - 1 + lane);
            }
        }
        __syncthreads();
        // epilogue: flush final chunk
        {
            const int fb = (NCHUNK - 1) & 1;
            const int a  = (NCHUNK - 1) * 8;
#pragma unroll
            for (int it = 0; it < 16; it++) {
                float v = s_act[fb][it * 4 + fr][fc];
                int col = a + off[it];
                if ((unsigned)col < W) g_unskew[Bidx[it] + a] = v;
            }
            if (prod) {
                if (lane < 8) g_bound[b][a + lane] = s_act[fb][RPB - 1][lane];
                __threadfence();
                __syncwarp();
                if (lane == 0) rel_store(&g_progress[b], NCHUNK * 8);
            }
        }
    }
}

// out[f][o] = dot(unskew_flat[f], fc_w[o]) + fc_b[o]; 10 warps, one per output
__global__ void fc_kernel(const float* __restrict__ fc_w, const float* __restrict__ fc_b,
                          float* __restrict__ out) {
    __shared__ float4 sact[FC_IN / 4];
    const int f = blockIdx.x;
    const float4* src = (const float4*)(g_unskew + (size_t)f * FC_IN);
    if (threadIdx.x < FC_IN / 4) sact[threadIdx.x] = src[threadIdx.x];
    __syncthreads();
    const int wid  = threadIdx.x >> 5;
    const int lane = threadIdx.x & 31;
    if (wid < FC_OUT) {
        const float4* wr = (const float4*)(fc_w + (size_t)wid * FC_IN);
        float acc = 0.0f;
#pragma unroll
        for (int i = 0; i < 8; i++) {
            float4 a  = sact[lane + i * 32];
            float4 wv = wr[lane + i * 32];
            acc = fmaf(a.x, wv.x, acc);
            acc = fmaf(a.y, wv.y, acc);
            acc = fmaf(a.z, wv.z, acc);
            acc = fmaf(a.w, wv.w, acc);
        }
#pragma unroll
        for (int s = 16; s > 0; s >>= 1) acc += __shfl_down_sync(0xffffffffu, acc, s);
        if (lane == 0) out[f * FC_OUT + wid] = acc + fc_b[wid];
    }
}

extern "C" void kernel_launch(void* const* d_in, const int* in_sizes, int n_in,
                              void* d_out, int out_size) {
    const float* x       = (const float*)d_in[0];
    const float* w_in    = (const float*)d_in[1];
    const float* b_in    = (const float*)d_in[2];
    const float* w_state = (const float*)d_in[3];
    const float* b_state = (const float*)d_in[4];
    const float* fc_w    = (const float*)d_in[5];
    const float* fc_b    = (const float*)d_in[6];
    (void)in_sizes; (void)n_in; (void)out_size;

    init_kernel<<<1, 32>>>();                          // reset pipeline flags per replay
    scan_kernel<<<NBLK, 64>>>(x, w_in, b_in, w_state, b_state);
    fc_kernel<<<NFLAT, 320>>>(fc_w, fc_b, (float*)d_out);
}

// round 7
// speedup vs baseline: 1.3185x; 1.1959x over previous
#include <cuda_runtime.h>
#include <cstdint>
#include <cstddef>

#define NBLK   32
#define RPB    64               // rows per block
#define W      2048
#define H      2048
#define WSK    4096             // 4095 real skewed columns, padded to 4096
#define CH     8
#define NCHUNK (WSK / CH)       // 512
#define FC_IN  1024
#define FC_OUT 10
#define NFLAT  ((H * W) / FC_IN) // 4096

// ---- scratch (device globals: no runtime allocation allowed) ----
__device__ float g_unskew[(size_t)H * W];     // unskewed activations, row-major [r][c]
__device__ float g_bound[NBLK][WSK];          // last-row value per column per block
__device__ int   g_progress[NBLK][32];        // PADDED: one 128B L2 line per block
                                              // (shared-line strong ops serialize at LTS)

// ---- accurate tanh: (e-1)*rcp(e+1), e = 2^(min(z,10)*2*log2 e). abs err ~1e-7 ----
__device__ __forceinline__ float fast_tanh(float z) {
    float zc = fminf(z, 10.0f);
    float t = zc * 2.8853900817779268f;
    float e;
    asm("ex2.approx.f32 %0, %1;" : "=f"(e) : "f"(t));
    float num = e - 1.0f;
    float den = e + 1.0f;
    float r;
    asm("rcp.approx.f32 %0, %1;" : "=f"(r) : "f"(den));
    return num * r;
}

__device__ __forceinline__ int acq_load(const int* p) {
    int v;
    asm volatile("ld.acquire.gpu.global.s32 %0, [%1];" : "=r"(v) : "l"(p) : "memory");
    return v;
}
__device__ __forceinline__ void rel_store(int* p, int v) {
    asm volatile("st.release.gpu.global.s32 [%0], %1;" :: "l"(p), "r"(v) : "memory");
}
// L2-only load: immune to stale L1 lines for producer-written boundary values
__device__ __forceinline__ float ldcg(const float* p) {
    float v;
    asm volatile("ld.global.cg.f32 %0, [%1];" : "=f"(v) : "l"(p));
    return v;
}

__global__ void init_kernel() {
    ((int*)g_progress)[threadIdx.x] = 0;      // 1024 threads clear all padded flags
}

// 2 warps per block. Warp 0: compute only (lane l owns rows base+2l, base+2l+1).
// Warp 1: all global memory traffic, coalesced, staged through shared tiles.
__global__ void __launch_bounds__(64, 1) scan_kernel(
    const float* __restrict__ img, const float* __restrict__ w_in,
    const float* __restrict__ b_in, const float* __restrict__ w_state,
    const float* __restrict__ b_state)
{
    __shared__ float s_img[3][RPB][CH];   // image tiles (chunk n in buf n%3)
    __shared__ float s_act[2][RPB][CH];   // activation tiles (chunk n in buf n&1)
    __shared__ float s_bnd[3][CH];        // boundary vals (chunk n in buf n%3)

    const int b    = blockIdx.x;
    const int tid  = threadIdx.x;
    const int lane = tid & 31;
    const int base = b * RPB;

    if (tid < 32) {
        // ================= compute warp =================
        const float w  = w_in[0];
        const float k0 = w_state[0];
        const float k1 = w_state[1];
        const float cb = b_in[0] + b_state[0];
        float hA = 0.0f, hB = 0.0f;       // rows base+2*lane, base+2*lane+1

        const int rA = 2 * lane;
        const int rB = rA + 1;

        for (int n = 0; n < NCHUNK; n++) {
            __syncthreads();              // img/bnd for chunk n ready; act[n&1] free
            const int ib = n % 3;
            float4 iA0 = *(const float4*)&s_img[ib][rA][0];
            float4 iA1 = *(const float4*)&s_img[ib][rA][4];
            float4 iB0 = *(const float4*)&s_img[ib][rB][0];
            float4 iB1 = *(const float4*)&s_img[ib][rB][4];
            float bcur = s_bnd[ib][lane & 7];    // lane k<8 holds bound idx n*8-1+k
            float iA[8] = {iA0.x, iA0.y, iA0.z, iA0.w, iA1.x, iA1.y, iA1.z, iA1.w};
            float iB[8] = {iB0.x, iB0.y, iB0.z, iB0.w, iB1.x, iB1.y, iB1.z, iB1.w};
            float aA[8], aB[8];
#pragma unroll
            for (int cc = 0; cc < CH; cc++) {
                float bv  = __shfl_sync(0xffffffffu, bcur, cc);  // bound for col j-1
                float upw = __shfl_up_sync(0xffffffffu, hB, 1);  // row rA-1 (old)
                float up  = (lane == 0) ? bv : upw;
                float zA = fmaf(k0, up, fmaf(k1, hA, fmaf(w, iA[cc], cb)));
                float zB = fmaf(k0, hA, fmaf(k1, hB, fmaf(w, iB[cc], cb))); // old hA
                hA = fast_tanh(zA);
                hB = fast_tanh(zB);
                aA[cc] = hA; aB[cc] = hB;
            }
            const int ab = n & 1;
            *(float4*)&s_act[ab][rA][0] = make_float4(aA[0], aA[1], aA[2], aA[3]);
            *(float4*)&s_act[ab][rA][4] = make_float4(aA[4], aA[5], aA[6], aA[7]);
            *(float4*)&s_act[ab][rB][0] = make_float4(aB[0], aB[1], aB[2], aB[3]);
            *(float4*)&s_act[ab][rB][4] = make_float4(aB[4], aB[5], aB[6], aB[7]);
        }
        __syncthreads();                  // final: hand last tile to warp 1
    } else {
        // ================= memory warp =================
        const int fr = lane >> 3;         // 0..3 : row sub-index
        const int fc = lane & 7;          // 0..7 : column within chunk
        int Bidx[16], off[16];            // per-it constants; chunk m addr = Bidx+8m
#pragma unroll
        for (int it = 0; it < 16; it++) {
            int g_row = base + it * 4 + fr;
            off[it]  = fc - g_row;                 // col = 8*m + off
            Bidx[it] = g_row * (W - 1) + fc;       // addr = Bidx + 8*m
        }
        const float* ub = (b > 0) ? g_bound[b - 1] : g_bound[0];
        const int* upflag = (b > 0) ? &g_progress[b - 1][0] : &g_progress[0][0];
        const bool prod = (b < NBLK - 1);
        int kn = 0;

        if (lane < 8) { s_bnd[0][lane] = 0.f; s_bnd[1][lane] = 0.f; s_bnd[2][lane] = 0.f; }

        // prologue: img chunks 0,1 -> smem; chunk 2 -> regs
        float rimg[16];
#pragma unroll
        for (int it = 0; it < 16; it++) {
            int row = it * 4 + fr;
            { int col = off[it];      s_img[0][row][fc] = ((unsigned)col < W) ? img[Bidx[it]]      : 0.f; }
            { int col = 8 + off[it];  s_img[1][row][fc] = ((unsigned)col < W) ? img[Bidx[it] + 8]  : 0.f; }
            { int col = 16 + off[it]; rimg[it]          = ((unsigned)col < W) ? img[Bidx[it] + 16] : 0.f; }
        }
        float rbnd = 0.0f;
        if (b > 0) {                       // boundary chunks 0,1 -> smem; 2 -> reg
            while (kn < 7)  kn = acq_load(upflag);
            if (lane < 8) { int idx = lane - 1; s_bnd[0][lane] = (idx >= 0) ? ldcg(ub + idx) : 0.f; }
            while (kn < 15) kn = acq_load(upflag);
            if (lane < 8) s_bnd[1][lane] = ldcg(ub + 7 + lane);
            while (kn < 23) kn = acq_load(upflag);
            if (lane < 8) rbnd = ldcg(ub + 15 + lane);
        }

        for (int n = 0; n < NCHUNK; n++) {
            __syncthreads();
            const int m2 = n + 2, m3 = n + 3;
            // publish staged chunk n+2 (img + bnd) into smem
            if (m2 < NCHUNK) {
                const int bi = m2 % 3;
#pragma unroll
                for (int it = 0; it < 16; it++) s_img[bi][it * 4 + fr][fc] = rimg[it];
                if (b > 0 && lane < 8) s_bnd[bi][lane] = rbnd;
            }
            // issue loads for chunk n+3 (consumed next window: full latency slack)
            if (m3 < NCHUNK) {
                const int a = m3 * 8;
#pragma unroll
                for (int it = 0; it < 16; it++) {
                    int col = a + off[it];
                    rimg[it] = ((unsigned)col < W) ? img[Bidx[it] + a] : 0.f;
                }
            }
            // flush activation tile of chunk n-1 (coalesced) + publish boundary
            if (n >= 1) {
                const int fb = (n - 1) & 1;
                const int a  = (n - 1) * 8;
#pragma unroll
                for (int it = 0; it < 16; it++) {
                    float v = s_act[fb][it * 4 + fr][fc];
                    int col = a + off[it];
                    if ((unsigned)col < W) g_unskew[Bidx[it] + a] = v;
                }
                if (prod) {
                    if (lane < 8) g_bound[b][a + lane] = s_act[fb][RPB - 1][lane];
                    __syncwarp();                      // order lanes' data stores
                    if (lane == 0) rel_store(&g_progress[b][0], n * 8);  // release
                }
            }
            // fetch boundary chunk n+3 into reg (usually zero polls: kn caches)
            if (b > 0 && m3 < NCHUNK) {
                const int need = m3 * 8 + 7;
                while (kn < need) kn = acq_load(upflag);
                if (lane < 8) rbnd = ldcg(ub + m3 * 8 - 1 + lane);
            }
        }
        __syncthreads();
        // epilogue: flush final chunk
        {
            const int fb = (NCHUNK - 1) & 1;
            const int a  = (NCHUNK - 1) * 8;
#pragma unroll
            for (int it = 0; it < 16; it++) {
                float v = s_act[fb][it * 4 + fr][fc];
                int col = a + off[it];
                if ((unsigned)col < W) g_unskew[Bidx[it] + a] = v;
            }
            if (prod) {
                if (lane < 8) g_bound[b][a + lane] = s_act[fb][RPB - 1][lane];
                __syncwarp();
                if (lane == 0) rel_store(&g_progress[b][0], NCHUNK * 8);
            }
        }
    }
}

// out[f][o] = dot(unskew_flat[f], fc_w[o]) + fc_b[o]; 10 warps, one per output
__global__ void fc_kernel(const float* __restrict__ fc_w, const float* __restrict__ fc_b,
                          float* __restrict__ out) {
    __shared__ float4 sact[FC_IN / 4];
    const int f = blockIdx.x;
    const float4* src = (const float4*)(g_unskew + (size_t)f * FC_IN);
    if (threadIdx.x < FC_IN / 4) sact[threadIdx.x] = src[threadIdx.x];
    __syncthreads();
    const int wid  = threadIdx.x >> 5;
    const int lane = threadIdx.x & 31;
    if (wid < FC_OUT) {
        const float4* wr = (const float4*)(fc_w + (size_t)wid * FC_IN);
        float acc = 0.0f;
#pragma unroll
        for (int i = 0; i < 8; i++) {
            float4 a  = sact[lane + i * 32];
            float4 wv = wr[lane + i * 32];
            acc = fmaf(a.x, wv.x, acc);
            acc = fmaf(a.y, wv.y, acc);
            acc = fmaf(a.z, wv.z, acc);
            acc = fmaf(a.w, wv.w, acc);
        }
#pragma unroll
        for (int s = 16; s > 0; s >>= 1) acc += __shfl_down_sync(0xffffffffu, acc, s);
        if (lane == 0) out[f * FC_OUT + wid] = acc + fc_b[wid];
    }
}

extern "C" void kernel_launch(void* const* d_in, const int* in_sizes, int n_in,
                              void* d_out, int out_size) {
    const float* x       = (const float*)d_in[0];
    const float* w_in    = (const float*)d_in[1];
    const float* b_in    = (const float*)d_in[2];
    const float* w_state = (const float*)d_in[3];
    const float* b_state = (const float*)d_in[4];
    const float* fc_w    = (const float*)d_in[5];
    const float* fc_b    = (const float*)d_in[6];
    (void)in_sizes; (void)n_in; (void)out_size;

    init_kernel<<<1, NBLK * 32>>>();                   // reset pipeline flags per replay
    scan_kernel<<<NBLK, 64>>>(x, w_in, b_in, w_state, b_state);
    fc_kernel<<<NFLAT, 320>>>(fc_w, fc_b, (float*)d_out);
}

// round 9
// speedup vs baseline: 2.2315x; 1.6924x over previous
#include <cuda_runtime.h>
#include <cstdint>
#include <cstddef>

#define NBLK   32
#define RPB    64               // rows per block
#define W      2048
#define H      2048
#define WSK    4096             // 4095 real skewed columns, padded to 4096
#define CH     16
#define NCHUNK (WSK / CH)       // 256
#define FC_IN  1024
#define FC_OUT 10
#define NFLAT  ((H * W) / FC_IN) // 4096

// ---- scratch (device globals: no runtime allocation allowed) ----
__device__ float g_unskew[(size_t)H * W];     // unskewed activations, row-major [r][c]
__device__ float g_bound[NBLK][WSK];          // last-row value per column per block
__device__ int   g_progress[NBLK][32];        // one 128B L2 line per block

// ---- tanh(z) = 1 - 2*rcp(exp2(z*2log2e)+1). Saturates safely at +/-1. ----
__device__ __forceinline__ float fast_tanh(float z) {
    float t = z * 2.8853900817779268f;        // 2*log2(e)
    float e;
    asm("ex2.approx.f32 %0, %1;" : "=f"(e) : "f"(t));
    float den = e + 1.0f;
    float r;
    asm("rcp.approx.f32 %0, %1;" : "=f"(r) : "f"(den));
    return fmaf(-2.0f, r, 1.0f);
}

__device__ __forceinline__ int acq_load(const int* p) {
    int v;
    asm volatile("ld.acquire.gpu.global.s32 %0, [%1];" : "=r"(v) : "l"(p) : "memory");
    return v;
}
__device__ __forceinline__ void rel_store(int* p, int v) {
    asm volatile("st.release.gpu.global.s32 [%0], %1;" :: "l"(p), "r"(v) : "memory");
}
// L2-only load: immune to stale L1 lines for producer-written data
__device__ __forceinline__ float ldcg(const float* p) {
    float v;
    asm volatile("ld.global.cg.f32 %0, [%1];" : "=f"(v) : "l"(p));
    return v;
}

__global__ void init_kernel() {
    ((int*)g_progress)[threadIdx.x] = 0;      // NBLK*32 threads clear all flags
}

// 2 warps per block. Warp 0: compute (lane l owns rows base+2l, base+2l+1) and
// publishes the block's boundary row directly (lane 31). Warp 1: all image /
// unskew global traffic + boundary consumption, staged through swizzled tiles.
// Tile layout: [CH][RPB], element (row,cc) stored at [cc][row ^ (4*(cc&7))].
// Writer lanes (fr=lane>>3, fc=lane&7) and reader float2 accesses are both
// bank-conflict-free under this swizzle.
__global__ void __launch_bounds__(64, 1) scan_kernel(
    const float* __restrict__ img, const float* __restrict__ w_in,
    const float* __restrict__ b_in, const float* __restrict__ w_state,
    const float* __restrict__ b_state)
{
    __shared__ __align__(16) float s_img[3][CH][RPB];  // chunk n in buf n%3
    __shared__ __align__(16) float s_act[2][CH][RPB];  // chunk n in buf n&1
    __shared__ __align__(16) float s_bnd[2][CH];       // chunk n in buf n&1

    const int b    = blockIdx.x;
    const int tid  = threadIdx.x;
    const int lane = tid & 31;
    const int base = b * RPB;

    if (tid < 32) {
        // ================= compute warp =================
        const float w  = w_in[0];
        const float k0 = w_state[0];
        const float k1 = w_state[1];
        const float cb = b_in[0] + b_state[0];
        float hA = 0.0f, hB = 0.0f;       // rows base+2*lane, base+2*lane+1
        float* brow = g_bound[b];

        for (int n = 0; n < NCHUNK; n++) {
            __syncthreads();              // img/bnd chunk n ready; act[n&1] free
            const int ib = n % 3;
            float iA[CH], iB[CH];
#pragma unroll
            for (int cc = 0; cc < CH; cc++) {
                float2 p = *(const float2*)&s_img[ib][cc][(2 * lane) ^ (4 * (cc & 7))];
                iA[cc] = p.x; iB[cc] = p.y;
            }
            float bc = s_bnd[n & 1][lane & 15];  // lane k<16: bound idx n*16-1+k
            float sA[CH], sB[CH];
#pragma unroll
            for (int cc = 0; cc < CH; cc++) {
                float bv  = __shfl_sync(0xffffffffu, bc, cc);   // bound col j-1
                float upw = __shfl_up_sync(0xffffffffu, hB, 1); // row rA-1 (old)
                float up  = (lane == 0) ? bv : upw;
                float zA = fmaf(k0, up, fmaf(k1, hA, fmaf(w, iA[cc], cb)));
                float zB = fmaf(k0, hA, fmaf(k1, hB, fmaf(w, iB[cc], cb))); // old hA
                hA = fast_tanh(zA);
                hB = fast_tanh(zB);
                sA[cc] = hA; sB[cc] = hB;
            }
            const int ab = n & 1;
#pragma unroll
            for (int cc = 0; cc < CH; cc++) {
                float2 v = make_float2(sA[cc], sB[cc]);
                *(float2*)&s_act[ab][cc][(2 * lane) ^ (4 * (cc & 7))] = v;
            }
            // lane 31 (row base+63 = block's last row) publishes boundary now:
            // shortest possible producer->consumer path (1-window lag).
            if (lane == 31) {
                float4* dst = (float4*)(brow + n * CH);
                dst[0] = make_float4(sB[0],  sB[1],  sB[2],  sB[3]);
                dst[1] = make_float4(sB[4],  sB[5],  sB[6],  sB[7]);
                dst[2] = make_float4(sB[8],  sB[9],  sB[10], sB[11]);
                dst[3] = make_float4(sB[12], sB[13], sB[14], sB[15]);
                rel_store(&g_progress[b][0], (n + 1) * CH);     // release: orders STGs
            }
        }
        __syncthreads();                  // final: hand last act tile to warp 1
    } else {
        // ================= memory warp =================
        const int fr = lane >> 3;         // 0..3 : row sub-index within group
        const int fc = lane & 7;          // 0..7 : column sub-index
        int Bidx[16], off[16], swz[16];   // chunk m: global addr = Bidx + 16*m (+8)
#pragma unroll
        for (int it = 0; it < 16; it++) {
            int gr   = base + it * 4 + fr;
            off[it]  = fc - gr;                    // global col = a + off (+8)
            Bidx[it] = gr * (W - 1) + fc;          // unskew/img addr = Bidx + a (+8)
            swz[it]  = (it * 4 + fr) ^ (4 * fc);   // swizzled row position
        }
        const float* ub     = (b > 0) ? g_bound[b - 1] : g_bound[0];
        const int*   upflag = (b > 0) ? &g_progress[b - 1][0] : &g_progress[0][0];
        int kn = 0;

        // prologue: img chunks 0,1 -> smem; chunk 2 -> regs
        float rg[32];
#pragma unroll
        for (int it = 0; it < 16; it++) {
            int o = off[it];
            { int c = o;      s_img[0][fc][swz[it]]     = ((unsigned)c < W) ? img[Bidx[it]]      : 0.f; }
            { int c = o + 8;  s_img[0][fc+8][swz[it]]   = ((unsigned)c < W) ? img[Bidx[it] + 8]  : 0.f; }
            { int c = o + 16; s_img[1][fc][swz[it]]     = ((unsigned)c < W) ? img[Bidx[it] + 16] : 0.f; }
            { int c = o + 24; s_img[1][fc+8][swz[it]]   = ((unsigned)c < W) ? img[Bidx[it] + 24] : 0.f; }
            { int c = o + 32; rg[2*it]                  = ((unsigned)c < W) ? img[Bidx[it] + 32] : 0.f; }
            { int c = o + 40; rg[2*it+1]                = ((unsigned)c < W) ? img[Bidx[it] + 40] : 0.f; }
        }
        // boundary chunk 0 (indices -1..14); zero-fill for block 0
        if (lane < CH) { s_bnd[0][lane] = 0.f; s_bnd[1][lane] = 0.f; }
        if (b > 0) {
            while (kn < CH - 1) kn = acq_load(upflag);
            if (lane < CH) s_bnd[0][lane] = (lane > 0) ? ldcg(ub + lane - 1) : 0.f;
        }

        for (int n = 0; n < NCHUNK; n++) {
            __syncthreads();
            const int m2 = n + 2, m3 = n + 3;
            // publish staged img chunk n+2 into smem
            if (m2 < NCHUNK) {
                const int bi = m2 % 3;
#pragma unroll
                for (int it = 0; it < 16; it++) {
                    s_img[bi][fc][swz[it]]   = rg[2*it];
                    s_img[bi][fc+8][swz[it]] = rg[2*it+1];
                }
            }
            // issue img loads for chunk n+3 (one full window of latency slack)
            if (m3 < NCHUNK) {
                const int a = m3 * CH;
#pragma unroll
                for (int it = 0; it < 16; it++) {
                    int c0 = a + off[it];
                    rg[2*it]   = ((unsigned)c0 < W)       ? img[Bidx[it] + a]     : 0.f;
                    rg[2*it+1] = ((unsigned)(c0+8) < W)   ? img[Bidx[it] + a + 8] : 0.f;
                }
            }
            // flush activation tile of chunk n-1 (coalesced)
            if (n >= 1) {
                const int fb = (n - 1) & 1;
                const int a  = (n - 1) * CH;
#pragma unroll
                for (int it = 0; it < 16; it++) {
                    int c0 = a + off[it];
                    float v0 = s_act[fb][fc][swz[it]];
                    float v1 = s_act[fb][fc+8][swz[it]];
                    if ((unsigned)c0 < W)     g_unskew[Bidx[it] + a]     = v0;
                    if ((unsigned)(c0+8) < W) g_unskew[Bidx[it] + a + 8] = v1;
                }
            }
            // fetch boundary chunk n+1 into s_bnd[(n+1)&1] (distance-1: producer
            // publishes from its compute warp, so it's ~1 window ahead)
            if (b > 0 && n + 1 < NCHUNK) {
                const int need = (n + 1) * CH + (CH - 1);
                while (kn < need) kn = acq_load(upflag);
                if (lane < CH) s_bnd[(n + 1) & 1][lane] = ldcg(ub + (n + 1) * CH - 1 + lane);
            }
        }
        __syncthreads();
        // epilogue: flush final activation chunk
        {
            const int fb = (NCHUNK - 1) & 1;
            const int a  = (NCHUNK - 1) * CH;
#pragma unroll
            for (int it = 0; it < 16; it++) {
                int c0 = a + off[it];
                float v0 = s_act[fb][fc][swz[it]];
                float v1 = s_act[fb][fc+8][swz[it]];
                if ((unsigned)c0 < W)     g_unskew[Bidx[it] + a]     = v0;
                if ((unsigned)(c0+8) < W) g_unskew[Bidx[it] + a + 8] = v1;
            }
        }
    }
}

// out[f][o] = dot(unskew_flat[f], fc_w[o]) + fc_b[o]; 10 warps, one per output
__global__ void fc_kernel(const float* __restrict__ fc_w, const float* __restrict__ fc_b,
                          float* __restrict__ out) {
    __shared__ float4 sact[FC_IN / 4];
    const int f = blockIdx.x;
    const float4* src = (const float4*)(g_unskew + (size_t)f * FC_IN);
    if (threadIdx.x < FC_IN / 4) sact[threadIdx.x] = src[threadIdx.x];
    __syncthreads();
    const int wid  = threadIdx.x >> 5;
    const int lane = threadIdx.x & 31;
    if (wid < FC_OUT) {
        const float4* wr = (const float4*)(fc_w + (size_t)wid * FC_IN);
        float acc = 0.0f;
#pragma unroll
        for (int i = 0; i < 8; i++) {
            float4 a  = sact[lane + i * 32];
            float4 wv = wr[lane + i * 32];
            acc = fmaf(a.x, wv.x, acc);
            acc = fmaf(a.y, wv.y, acc);
            acc = fmaf(a.z, wv.z, acc);
            acc = fmaf(a.w, wv.w, acc);
        }
#pragma unroll
        for (int s = 16; s > 0; s >>= 1) acc += __shfl_down_sync(0xffffffffu, acc, s);
        if (lane == 0) out[f * FC_OUT + wid] = acc + fc_b[wid];
    }
}

extern "C" void kernel_launch(void* const* d_in, const int* in_sizes, int n_in,
                              void* d_out, int out_size) {
    const float* x       = (const float*)d_in[0];
    const float* w_in    = (const float*)d_in[1];
    const float* b_in    = (const float*)d_in[2];
    const float* w_state = (const float*)d_in[3];
    const float* b_state = (const float*)d_in[4];
    const float* fc_w    = (const float*)d_in[5];
    const float* fc_b    = (const float*)d_in[6];
    (void)in_sizes; (void)n_in; (void)out_size;

    init_kernel<<<1, NBLK * 32>>>();                   // reset pipeline flags per replay
    scan_kernel<<<NBLK, 64>>>(x, w_in, b_in, w_state, b_state);
    fc_kernel<<<NFLAT, 320>>>(fc_w, fc_b, (float*)d_out);
}

// round 12
// speedup vs baseline: 2.3862x; 1.0693x over previous
#include <cuda_runtime.h>
#include <cstdint>
#include <cstddef>

#define NBLK   32
#define RPB    64               // rows per block
#define W      2048
#define H      2048
#define WSK    4096             // 4095 real skewed columns, padded to 4096
#define CH     16
#define NCHUNK (WSK / CH)       // 256
#define FC_IN  1024
#define FC_OUT 10
#define NFLAT  ((H * W) / FC_IN) // 4096

// ---- scratch (device globals: no runtime allocation allowed) ----
__device__ float g_unskew[(size_t)H * W];     // unskewed activations, row-major [r][c]
__device__ float g_bound[NBLK][WSK];          // last-row h value per column per block
__device__ int   g_progress[NBLK][32];        // one 128B L2 line per block

#define C2LOG2E 2.8853900817779268f           // 2*log2(e)

__device__ __forceinline__ int acq_load(const int* p) {
    int v;
    asm volatile("ld.acquire.gpu.global.s32 %0, [%1];" : "=r"(v) : "l"(p) : "memory");
    return v;
}
__device__ __forceinline__ void rel_store(int* p, int v) {
    asm volatile("st.release.gpu.global.s32 [%0], %1;" :: "l"(p), "r"(v) : "memory");
}
// L2-only load: immune to stale L1 lines for producer-written data
__device__ __forceinline__ float ldcg(const float* p) {
    float v;
    asm volatile("ld.global.cg.f32 %0, [%1];" : "=f"(v) : "l"(p));
    return v;
}
__device__ __forceinline__ float ex2f(float t) {
    float e;
    asm("ex2.approx.f32 %0, %1;" : "=f"(e) : "f"(t));
    return e;
}
__device__ __forceinline__ float rcpf(float d) {
    float r;
    asm("rcp.approx.f32 %0, %1;" : "=f"(r) : "f"(d));
    return r;
}

// Recurrence in r-space: h = tanh(z) = 1 - 2*r with r = rcp(exp2(z*2log2e)+1).
// t(z) accumulates directly: t = pre + n2k0c*r_up + n2k1c*r_self
// where pre = (w*img + cb + k0 + k1)*2log2e (staged by the memory warp),
// n2kXc = -2*kX*2log2e. Saturates safely (e->inf => r->0 => h->1; e->0 => h->-1).

// 2 warps per block. Warp 0: compute (lane l owns rows base+2l, base+2l+1) and
// publishes the block's boundary row directly (lane 31). Warp 1: all image /
// unskew global traffic + boundary consumption, staged through swizzled tiles.
// Tile layout: [CH][RPB], element (row,cc) stored at [cc][row ^ (4*(cc&7))];
// both the writer pattern and the compute warp's float2 reads are conflict-free.
__global__ void __launch_bounds__(64, 1) scan_kernel(
    const float* __restrict__ img, const float* __restrict__ w_in,
    const float* __restrict__ b_in, const float* __restrict__ w_state,
    const float* __restrict__ b_state)
{
    __shared__ __align__(16) float s_img[3][CH][RPB];  // t-space inputs, chunk n in buf n%3
    __shared__ __align__(16) float s_act[2][CH][RPB];  // h-space acts, chunk n in buf n&1
    __shared__ __align__(16) float s_bnd[2][CH];       // r-space boundary, chunk n in buf n&1

    const int b    = blockIdx.x;
    const int tid  = threadIdx.x;
    const int lane = tid & 31;
    const int base = b * RPB;

    const float w  = w_in[0];
    const float k0 = w_state[0];
    const float k1 = w_state[1];
    const float cb = b_in[0] + b_state[0];

    if (tid < 32) {
        // ================= compute warp =================
        const float n2k0c = -2.0f * k0 * C2LOG2E;
        const float n2k1c = -2.0f * k1 * C2LOG2E;
        const float n2k0c_up = (lane == 0) ? 0.0f : n2k0c;  // lane0: ignore shfl_up
        const float n2k0c_b  = (lane == 0) ? n2k0c : 0.0f;  // lane0: use boundary
        float rA = 0.5f, rB = 0.5f;       // r of h=0
        float* brow = g_bound[b];

        for (int n = 0; n < NCHUNK; n++) {
            __syncthreads();              // img/bnd chunk n ready; act[n&1] free
            const int ib = n % 3;
            float pA[CH], pB[CH];
#pragma unroll
            for (int cc = 0; cc < CH; cc++) {
                float2 p = *(const float2*)&s_img[ib][cc][(2 * lane) ^ (4 * (cc & 7))];
                pA[cc] = p.x; pB[cc] = p.y;
            }
            float bc = s_bnd[n & 1][lane & 15];  // r-space bound, idx n*16-1+k
            float sA[CH], sB[CH];
#pragma unroll
            for (int cc = 0; cc < CH; cc++) {
                float bv = __shfl_sync(0xffffffffu, bc, cc);    // off-chain (hoists)
                float up = __shfl_up_sync(0xffffffffu, rB, 1);  // chain: rB(cc-1)
                float tA = fmaf(n2k0c_up, up,
                           fmaf(n2k0c_b, bv, fmaf(n2k1c, rA, pA[cc])));
                float tB = fmaf(n2k0c, rA, fmaf(n2k1c, rB, pB[cc])); // old rA,rB
                float rAn = rcpf(ex2f(tA) + 1.0f);
                float rBn = rcpf(ex2f(tB) + 1.0f);
                sA[cc] = fmaf(-2.0f, rAn, 1.0f);                // h-space (off-chain)
                sB[cc] = fmaf(-2.0f, rBn, 1.0f);
                rA = rAn; rB = rBn;
            }
            const int ab = n & 1;
#pragma unroll
            for (int cc = 0; cc < CH; cc++) {
                float2 v = make_float2(sA[cc], sB[cc]);
                *(float2*)&s_act[ab][cc][(2 * lane) ^ (4 * (cc & 7))] = v;
            }
            // lane 31 (row base+63 = block's last row) publishes boundary now:
            // shortest producer->consumer path (1-window lag).
            if (lane == 31) {
                float4* dst = (float4*)(brow + n * CH);
                dst[0] = make_float4(sB[0],  sB[1],  sB[2],  sB[3]);
                dst[1] = make_float4(sB[4],  sB[5],  sB[6],  sB[7]);
                dst[2] = make_float4(sB[8],  sB[9],  sB[10], sB[11]);
                dst[3] = make_float4(sB[12], sB[13], sB[14], sB[15]);
                rel_store(&g_progress[b][0], (n + 1) * CH);     // release: orders STGs
            }
        }
        __syncthreads();                  // final: hand last act tile to warp 1
    } else {
        // ================= memory warp =================
        const float wc    = w * C2LOG2E;
        const float basec = (cb + k0 + k1) * C2LOG2E;   // t-space out-of-band value
        const int fr = lane >> 3;         // 0..3 : row sub-index within group
        const int fc = lane & 7;          // 0..7 : column sub-index
        int Bidx[16], off[16], swz[16];   // chunk m: global addr = Bidx + 16*m (+8)
#pragma unroll
        for (int it = 0; it < 16; it++) {
            int gr   = base + it * 4 + fr;
            off[it]  = fc - gr;                    // global col = a + off (+8)
            Bidx[it] = gr * (W - 1) + fc;          // unskew/img addr = Bidx + a (+8)
            swz[it]  = (it * 4 + fr) ^ (4 * fc);   // swizzled row position
        }
        const float* ub     = (b > 0) ? g_bound[b - 1] : g_bound[0];
        const int*   upflag = (b > 0) ? &g_progress[b - 1][0] : &g_progress[0][0];
        int kn = 0;

        // prologue: img chunks 0,1 -> smem (t-space); chunk 2 -> regs (raw)
        float rg[32];
#pragma unroll
        for (int it = 0; it < 16; it++) {
            int o = off[it];
            { int c = o;      s_img[0][fc][swz[it]]   = ((unsigned)c < W) ? fmaf(wc, img[Bidx[it]],      basec) : basec; }
            { int c = o + 8;  s_img[0][fc+8][swz[it]] = ((unsigned)c < W) ? fmaf(wc, img[Bidx[it] + 8],  basec) : basec; }
            { int c = o + 16; s_img[1][fc][swz[it]]   = ((unsigned)c < W) ? fmaf(wc, img[Bidx[it] + 16], basec) : basec; }
            { int c = o + 24; s_img[1][fc+8][swz[it]] = ((unsigned)c < W) ? fmaf(wc, img[Bidx[it] + 24], basec) : basec; }
            { int c = o + 32; rg[2*it]                = ((unsigned)c < W) ? img[Bidx[it] + 32] : 0.f; }
            { int c = o + 40; rg[2*it+1]              = ((unsigned)c < W) ? img[Bidx[it] + 40] : 0.f; }
        }
        // boundary chunk 0 (cols -1..14): r-space; h=0 -> r=0.5
        if (lane < CH) { s_bnd[0][lane] = 0.5f; s_bnd[1][lane] = 0.5f; }
        if (b > 0) {
            while (kn < CH - 1) kn = acq_load(upflag);
            if (lane > 0 && lane < CH)
                s_bnd[0][lane] = (1.0f - ldcg(ub + lane - 1)) * 0.5f;
        }

        for (int n = 0; n < NCHUNK; n++) {
            __syncthreads();
            const int m2 = n + 2, m3 = n + 3;
            // publish staged img chunk n+2 into smem (apply affine here)
            if (m2 < NCHUNK) {
                const int bi = m2 % 3;
#pragma unroll
                for (int it = 0; it < 16; it++) {
                    s_img[bi][fc][swz[it]]   = fmaf(wc, rg[2*it],   basec);
                    s_img[bi][fc+8][swz[it]] = fmaf(wc, rg[2*it+1], basec);
                }
            }
            // issue img loads for chunk n+3 (one full window of latency slack)
            if (m3 < NCHUNK) {
                const int a = m3 * CH;
#pragma unroll
                for (int it = 0; it < 16; it++) {
                    int c0 = a + off[it];
                    rg[2*it]   = ((unsigned)c0 < W)     ? img[Bidx[it] + a]     : 0.f;
                    rg[2*it+1] = ((unsigned)(c0+8) < W) ? img[Bidx[it] + a + 8] : 0.f;
                }
            }
            // flush activation tile of chunk n-1 (coalesced)
            if (n >= 1) {
                const int fb = (n - 1) & 1;
                const int a  = (n - 1) * CH;
#pragma unroll
                for (int it = 0; it < 16; it++) {
                    int c0 = a + off[it];
                    float v0 = s_act[fb][fc][swz[it]];
                    float v1 = s_act[fb][fc+8][swz[it]];
                    if ((unsigned)c0 < W)     g_unskew[Bidx[it] + a]     = v0;
                    if ((unsigned)(c0+8) < W) g_unskew[Bidx[it] + a + 8] = v1;
                }
            }
            // fetch boundary chunk n+1, convert h->r (distance-1 lag)
            if (b > 0 && n + 1 < NCHUNK) {
                const int need = (n + 1) * CH + (CH - 1);
                while (kn < need) kn = acq_load(upflag);
                if (lane < CH)
                    s_bnd[(n + 1) & 1][lane] =
                        (1.0f - ldcg(ub + (n + 1) * CH - 1 + lane)) * 0.5f;
            }
        }
        __syncthreads();
        // epilogue: flush final activation chunk
        {
            const int fb = (NCHUNK - 1) & 1;
            const int a  = (NCHUNK - 1) * CH;
#pragma unroll
            for (int it = 0; it < 16; it++) {
                int c0 = a + off[it];
                float v0 = s_act[fb][fc][swz[it]];
                float v1 = s_act[fb][fc+8][swz[it]];
                if ((unsigned)c0 < W)     g_unskew[Bidx[it] + a]     = v0;
                if ((unsigned)(c0+8) < W) g_unskew[Bidx[it] + a + 8] = v1;
            }
        }
    }
}

// out[f][o] = dot(unskew_flat[f], fc_w[o]) + fc_b[o]; 10 warps, one per output
__global__ void fc_kernel(const float* __restrict__ fc_w, const float* __restrict__ fc_b,
                          float* __restrict__ out) {
    __shared__ float4 sact[FC_IN / 4];
    const int f = blockIdx.x;
    const float4* src = (const float4*)(g_unskew + (size_t)f * FC_IN);
    if (threadIdx.x < FC_IN / 4) sact[threadIdx.x] = src[threadIdx.x];
    __syncthreads();
    const int wid  = threadIdx.x >> 5;
    const int lane = threadIdx.x & 31;
    if (wid < FC_OUT) {
        const float4* wr = (const float4*)(fc_w + (size_t)wid * FC_IN);
        float acc = 0.0f;
#pragma unroll
        for (int i = 0; i < 8; i++) {
            float4 a  = sact[lane + i * 32];
            float4 wv = wr[lane + i * 32];
            acc = fmaf(a.x, wv.x, acc);
            acc = fmaf(a.y, wv.y, acc);
            acc = fmaf(a.z, wv.z, acc);
            acc = fmaf(a.w, wv.w, acc);
        }
#pragma unroll
        for (int s = 16; s > 0; s >>= 1) acc += __shfl_down_sync(0xffffffffu, acc, s);
        if (lane == 0) out[f * FC_OUT + wid] = acc + fc_b[wid];
    }
}

// Clears progress flags AFTER each invocation so the next replay starts clean.
// (Globals are zero-initialized, so the very first call is also clean.)
__global__ void reset_kernel() {
    ((int*)g_progress)[threadIdx.x] = 0;
}

extern "C" void kernel_launch(void* const* d_in, const int* in_sizes, int n_in,
                              void* d_out, int out_size) {
    const float* x       = (const float*)d_in[0];
    const float* w_in    = (const float*)d_in[1];
    const float* b_in    = (const float*)d_in[2];
    const float* w_state = (const float*)d_in[3];
    const float* b_state = (const float*)d_in[4];
    const float* fc_w    = (const float*)d_in[5];
    const float* fc_b    = (const float*)d_in[6];
    (void)in_sizes; (void)n_in; (void)out_size;

    scan_kernel<<<NBLK, 64>>>(x, w_in, b_in, w_state, b_state);
    fc_kernel<<<NFLAT, 320>>>(fc_w, fc_b, (float*)d_out);
    reset_kernel<<<1, NBLK * 32>>>();   // flags clean for the next graph replay
}

// round 13
// speedup vs baseline: 3.0111x; 1.2619x over previous
#include <cuda_runtime.h>
#include <cstdint>
#include <cstddef>

#define NBLK   32
#define RPB    64               // rows per block
#define W      2048
#define H      2048
#define WSK    4096             // 4095 real skewed columns, padded to 4096
#define CH     16
#define NCHUNK (WSK / CH)       // 256
#define FC_IN  1024
#define FC_OUT 10
#define NFLAT  ((H * W) / FC_IN) // 4096

// ---- scratch (device globals: no runtime allocation allowed) ----
__device__ float g_unskew[(size_t)H * W];     // unskewed activations, row-major [r][c]
__device__ float g_bound[NBLK][WSK];          // last-row h value per column per block
__device__ int   g_progress[NBLK][32];        // one 128B L2 line per block

__device__ __forceinline__ int acq_load(const int* p) {
    int v;
    asm volatile("ld.acquire.gpu.global.s32 %0, [%1];" : "=r"(v) : "l"(p) : "memory");
    return v;
}
__device__ __forceinline__ void rel_store(int* p, int v) {
    asm volatile("st.release.gpu.global.s32 [%0], %1;" :: "l"(p), "r"(v) : "memory");
}
// L2-only load: immune to stale L1 lines for producer-written data
__device__ __forceinline__ float ldcg(const float* p) {
    float v;
    asm volatile("ld.global.cg.f32 %0, [%1];" : "=f"(v) : "l"(p));
    return v;
}
// Hardware tanh (MUFU.TANH, sm_75+): 1 op on the chain instead of ex2+add+rcp.
__device__ __forceinline__ float htanh(float z) {
    float r;
    asm("tanh.approx.f32 %0, %1;" : "=f"(r) : "f"(z));
    return r;
}

// 2 warps per block. Warp 0: compute (lane l owns rows base+2l, base+2l+1) and
// publishes the block's boundary row directly (lane 31). Warp 1: all image /
// unskew global traffic + boundary consumption, staged through swizzled tiles.
// Tile layout: [CH][RPB], element (row,cc) stored at [cc][row ^ (4*(cc&7))];
// both the writer pattern and the compute warp's float2 reads are conflict-free.
// Recurrence (plain h-space): h_new = tanh(k0*h_up + k1*h_self + pre),
// pre = w*img + cb staged by the memory warp (out-of-band cells = cb exactly).
__global__ void __launch_bounds__(64, 1) scan_kernel(
    const float* __restrict__ img, const float* __restrict__ w_in,
    const float* __restrict__ b_in, const float* __restrict__ w_state,
    const float* __restrict__ b_state)
{
    __shared__ __align__(16) float s_img[3][CH][RPB];  // pre-affine inputs, chunk n in buf n%3
    __shared__ __align__(16) float s_act[2][CH][RPB];  // h-space acts, chunk n in buf n&1
    __shared__ __align__(16) float s_bnd[2][CH];       // h-space boundary, chunk n in buf n&1

    const int b    = blockIdx.x;
    const int tid  = threadIdx.x;
    const int lane = tid & 31;
    const int base = b * RPB;

    const float w  = w_in[0];
    const float k0 = w_state[0];
    const float k1 = w_state[1];
    const float cb = b_in[0] + b_state[0];

    if (tid < 32) {
        // ================= compute warp =================
        const float k0_up = (lane == 0) ? 0.0f : k0;   // lane0: ignore shfl_up
        const float k0_b  = (lane == 0) ? k0   : 0.0f; // lane0: use boundary value
        float hA = 0.0f, hB = 0.0f;       // rows base+2*lane, base+2*lane+1
        float* brow = g_bound[b];

        for (int n = 0; n < NCHUNK; n++) {
            __syncthreads();              // img/bnd chunk n ready; act[n&1] free
            const int ib = n % 3;
            float pA[CH], pB[CH], bvs[CH];
            float bc = s_bnd[n & 1][lane & 15];   // boundary h, idx n*16-1+k
#pragma unroll
            for (int cc = 0; cc < CH; cc++) {
                float2 p = *(const float2*)&s_img[ib][cc][(2 * lane) ^ (4 * (cc & 7))];
                pA[cc] = p.x; pB[cc] = p.y;
                bvs[cc] = __shfl_sync(0xffffffffu, bc, cc);   // hoisted off the chain
            }
            float sA[CH], sB[CH];
#pragma unroll
            for (int cc = 0; cc < CH; cc++) {
                float up = __shfl_up_sync(0xffffffffu, hB, 1);  // chain: hB(cc-1)
                float zA = fmaf(k0_up, up,
                           fmaf(k0_b, bvs[cc], fmaf(k1, hA, pA[cc])));
                float zB = fmaf(k0, hA, fmaf(k1, hB, pB[cc]));  // old hA, hB
                hA = htanh(zA);
                hB = htanh(zB);
                sA[cc] = hA; sB[cc] = hB;
            }
            const int ab = n & 1;
#pragma unroll
            for (int cc = 0; cc < CH; cc++) {
                float2 v = make_float2(sA[cc], sB[cc]);
                *(float2*)&s_act[ab][cc][(2 * lane) ^ (4 * (cc & 7))] = v;
            }
            // lane 31 (row base+63 = block's last row) publishes boundary now:
            // shortest producer->consumer path (1-window lag).
            if (lane == 31) {
                float4* dst = (float4*)(brow + n * CH);
                dst[0] = make_float4(sB[0],  sB[1],  sB[2],  sB[3]);
                dst[1] = make_float4(sB[4],  sB[5],  sB[6],  sB[7]);
                dst[2] = make_float4(sB[8],  sB[9],  sB[10], sB[11]);
                dst[3] = make_float4(sB[12], sB[13], sB[14], sB[15]);
                rel_store(&g_progress[b][0], (n + 1) * CH);     // release: orders STGs
            }
        }
        __syncthreads();                  // final: hand last act tile to warp 1
    } else {
        // ================= memory warp =================
        const int fr = lane >> 3;         // 0..3 : row sub-index within group
        const int fc = lane & 7;          // 0..7 : column sub-index
        int Bidx[16], off[16], swz[16];   // chunk m: global addr = Bidx + 16*m (+8)
#pragma unroll
        for (int it = 0; it < 16; it++) {
            int gr   = base + it * 4 + fr;
            off[it]  = fc - gr;                    // global col = a + off (+8)
            Bidx[it] = gr * (W - 1) + fc;          // unskew/img addr = Bidx + a (+8)
            swz[it]  = (it * 4 + fr) ^ (4 * fc);   // swizzled row position
        }
        const float* ub     = (b > 0) ? g_bound[b - 1] : g_bound[0];
        const int*   upflag = (b > 0) ? &g_progress[b - 1][0] : &g_progress[0][0];
        int kn = 0;

        // prologue: img chunks 0,1 -> smem (pre-affine); chunk 2 -> regs (raw)
        float rg[32];
#pragma unroll
        for (int it = 0; it < 16; it++) {
            int o = off[it];
            { int c = o;      s_img[0][fc][swz[it]]   = ((unsigned)c < W) ? fmaf(w, img[Bidx[it]],      cb) : cb; }
            { int c = o + 8;  s_img[0][fc+8][swz[it]] = ((unsigned)c < W) ? fmaf(w, img[Bidx[it] + 8],  cb) : cb; }
            { int c = o + 16; s_img[1][fc][swz[it]]   = ((unsigned)c < W) ? fmaf(w, img[Bidx[it] + 16], cb) : cb; }
            { int c = o + 24; s_img[1][fc+8][swz[it]] = ((unsigned)c < W) ? fmaf(w, img[Bidx[it] + 24], cb) : cb; }
            { int c = o + 32; rg[2*it]                = ((unsigned)c < W) ? img[Bidx[it] + 32] : 0.f; }
            { int c = o + 40; rg[2*it+1]              = ((unsigned)c < W) ? img[Bidx[it] + 40] : 0.f; }
        }
        // boundary chunk 0 (cols -1..14): h=0 above the image
        if (lane < CH) { s_bnd[0][lane] = 0.f; s_bnd[1][lane] = 0.f; }
        if (b > 0) {
            while (kn < CH - 1) kn = acq_load(upflag);
            if (lane > 0 && lane < CH) s_bnd[0][lane] = ldcg(ub + lane - 1);
        }

        for (int n = 0; n < NCHUNK; n++) {
            __syncthreads();
            const int m2 = n + 2, m3 = n + 3;
            // publish staged img chunk n+2 into smem (apply affine here)
            if (m2 < NCHUNK) {
                const int bi = m2 % 3;
#pragma unroll
                for (int it = 0; it < 16; it++) {
                    s_img[bi][fc][swz[it]]   = fmaf(w, rg[2*it],   cb);
                    s_img[bi][fc+8][swz[it]] = fmaf(w, rg[2*it+1], cb);
                }
            }
            // issue img loads for chunk n+3 (one full window of latency slack)
            if (m3 < NCHUNK) {
                const int a = m3 * CH;
#pragma unroll
                for (int it = 0; it < 16; it++) {
                    int c0 = a + off[it];
                    rg[2*it]   = ((unsigned)c0 < W)     ? img[Bidx[it] + a]     : 0.f;
                    rg[2*it+1] = ((unsigned)(c0+8) < W) ? img[Bidx[it] + a + 8] : 0.f;
                }
            }
            // flush activation tile of chunk n-1 (coalesced)
            if (n >= 1) {
                const int fb = (n - 1) & 1;
                const int a  = (n - 1) * CH;
#pragma unroll
                for (int it = 0; it < 16; it++) {
                    int c0 = a + off[it];
                    float v0 = s_act[fb][fc][swz[it]];
                    float v1 = s_act[fb][fc+8][swz[it]];
                    if ((unsigned)c0 < W)     g_unskew[Bidx[it] + a]     = v0;
                    if ((unsigned)(c0+8) < W) g_unskew[Bidx[it] + a + 8] = v1;
                }
            }
            // fetch boundary chunk n+1 (distance-1 lag; producer = upstream compute warp)
            if (b > 0 && n + 1 < NCHUNK) {
                const int need = (n + 1) * CH + (CH - 1);
                while (kn < need) kn = acq_load(upflag);
                if (lane < CH)
                    s_bnd[(n + 1) & 1][lane] = ldcg(ub + (n + 1) * CH - 1 + lane);
            }
        }
        __syncthreads();
        // epilogue: flush final activation chunk
        {
            const int fb = (NCHUNK - 1) & 1;
            const int a  = (NCHUNK - 1) * CH;
#pragma unroll
            for (int it = 0; it < 16; it++) {
                int c0 = a + off[it];
                float v0 = s_act[fb][fc][swz[it]];
                float v1 = s_act[fb][fc+8][swz[it]];
                if ((unsigned)c0 < W)     g_unskew[Bidx[it] + a]     = v0;
                if ((unsigned)(c0+8) < W) g_unskew[Bidx[it] + a + 8] = v1;
            }
        }
    }
}

// out[f][o] = dot(unskew_flat[f], fc_w[o]) + fc_b[o]; 10 warps, one per output
__global__ void fc_kernel(const float* __restrict__ fc_w, const float* __restrict__ fc_b,
                          float* __restrict__ out) {
    __shared__ float4 sact[FC_IN / 4];
    const int f = blockIdx.x;
    const float4* src = (const float4*)(g_unskew + (size_t)f * FC_IN);
    if (threadIdx.x < FC_IN / 4) sact[threadIdx.x] = src[threadIdx.x];
    __syncthreads();
    const int wid  = threadIdx.x >> 5;
    const int lane = threadIdx.x & 31;
    if (wid < FC_OUT) {
        const float4* wr = (const float4*)(fc_w + (size_t)wid * FC_IN);
        float acc = 0.0f;
#pragma unroll
        for (int i = 0; i < 8; i++) {
            float4 a  = sact[lane + i * 32];
            float4 wv = wr[lane + i * 32];
            acc = fmaf(a.x, wv.x, acc);
            acc = fmaf(a.y, wv.y, acc);
            acc = fmaf(a.z, wv.z, acc);
            acc = fmaf(a.w, wv.w, acc);
        }
#pragma unroll
        for (int s = 16; s > 0; s >>= 1) acc += __shfl_down_sync(0xffffffffu, acc, s);
        if (lane == 0) out[f * FC_OUT + wid] = acc + fc_b[wid];
    }
}

// Clears progress flags AFTER each invocation so the next replay starts clean.
// (Globals are zero-initialized, so the very first call is also clean.)
__global__ void reset_kernel() {
    ((int*)g_progress)[threadIdx.x] = 0;
}

extern "C" void kernel_launch(void* const* d_in, const int* in_sizes, int n_in,
                              void* d_out, int out_size) {
    const float* x       = (const float*)d_in[0];
    const float* w_in    = (const float*)d_in[1];
    const float* b_in    = (const float*)d_in[2];
    const float* w_state = (const float*)d_in[3];
    const float* b_state = (const float*)d_in[4];
    const float* fc_w    = (const float*)d_in[5];
    const float* fc_b    = (const float*)d_in[6];
    (void)in_sizes; (void)n_in; (void)out_size;

    scan_kernel<<<NBLK, 64>>>(x, w_in, b_in, w_state, b_state);
    fc_kernel<<<NFLAT, 320>>>(fc_w, fc_b, (float*)d_out);
    reset_kernel<<<1, NBLK * 32>>>();   // flags clean for the next graph replay
}

// round 14
// speedup vs baseline: 3.1440x; 1.0441x over previous
#include <cuda_runtime.h>
#include <cstdint>
#include <cstddef>

#define NBLK   32
#define RPB    64               // rows per block
#define W      2048
#define H      2048
#define WSK    4096             // 4095 real skewed columns, padded to 4096
#define CH     16
#define NCHUNK (WSK / CH)       // 256
#define FC_IN  1024
#define FC_OUT 10
#define NFLAT  ((H * W) / FC_IN) // 4096

// ---- scratch (device globals: no runtime allocation allowed) ----
__device__ float g_unskew[(size_t)H * W];     // unskewed activations, row-major [r][c]
__device__ float g_bound[NBLK][WSK];          // last-row h value per column per block
__device__ int   g_progress[NBLK][32];        // one 128B L2 line per block

__device__ __forceinline__ int acq_load(const int* p) {
    int v;
    asm volatile("ld.acquire.gpu.global.s32 %0, [%1];" : "=r"(v) : "l"(p) : "memory");
    return v;
}
__device__ __forceinline__ void rel_store(int* p, int v) {
    asm volatile("st.release.gpu.global.s32 [%0], %1;" :: "l"(p), "r"(v) : "memory");
}
// L2-only load: immune to stale L1 lines for producer-written data
__device__ __forceinline__ float ldcg(const float* p) {
    float v;
    asm volatile("ld.global.cg.f32 %0, [%1];" : "=f"(v) : "l"(p));
    return v;
}
// Hardware tanh (MUFU.TANH): 1 op on the chain.
__device__ __forceinline__ float htanh(float z) {
    float r;
    asm("tanh.approx.f32 %0, %1;" : "=f"(r) : "f"(z));
    return r;
}

// 3 warps per block:
//   warp 0: compute (lane l owns rows base+2l, base+2l+1); lane 31 publishes
//           the block's boundary row (g_bound + release flag) directly.
//   warp 1: image load/stage + activation flush (coalesced, swizzled tiles).
//   warp 2: boundary sync only — polls upstream flag and fetches boundary
//           chunk n+2 at distance 2. Its serial L2 latency (~600cy) runs
//           concurrently with warps 0/1 instead of on the window critical path.
// Tile layout: [CH][RPB], element (row,cc) at [cc][row ^ (4*(cc&7))]; both the
// warp-1 write pattern and warp-0 float2 reads are bank-conflict-free.
// Recurrence: h_new = tanh(k0*h_up + k1*h_self + pre), pre = w*img + cb.
__global__ void __launch_bounds__(96, 1) scan_kernel(
    const float* __restrict__ img, const float* __restrict__ w_in,
    const float* __restrict__ b_in, const float* __restrict__ w_state,
    const float* __restrict__ b_state)
{
    __shared__ __align__(16) float s_img[3][CH][RPB];  // pre-affine inputs, chunk n in buf n%3
    __shared__ __align__(16) float s_act[2][CH][RPB];  // h-space acts, chunk n in buf n&1
    __shared__ __align__(16) float s_bnd[3][CH];       // boundary h, chunk n in buf n%3

    const int b    = blockIdx.x;
    const int tid  = threadIdx.x;
    const int lane = tid & 31;
    const int wid  = tid >> 5;
    const int base = b * RPB;

    const float w  = w_in[0];
    const float k0 = w_state[0];
    const float k1 = w_state[1];
    const float cb = b_in[0] + b_state[0];

    if (wid == 0) {
        // ================= compute warp =================
        const float k0_up = (lane == 0) ? 0.0f : k0;   // lane0: ignore shfl_up
        const float k0_b  = (lane == 0) ? k0   : 0.0f; // lane0: use boundary value
        float hA = 0.0f, hB = 0.0f;       // rows base+2*lane, base+2*lane+1
        float* brow = g_bound[b];

        for (int n = 0; n < NCHUNK; n++) {
            __syncthreads();              // img/bnd chunk n ready; act[n&1] free
            const int ib = n % 3;
            float pB[CH], qA[CH];
#pragma unroll
            for (int cc = 0; cc < CH; cc++) {
                float2 p = *(const float2*)&s_img[ib][cc][(2 * lane) ^ (4 * (cc & 7))];
                // fold boundary term (nonzero only on lane 0) off the chain;
                // s_bnd read is an LDS broadcast (no shuffle-unit traffic)
                qA[cc] = fmaf(k0_b, s_bnd[ib][cc], p.x);
                pB[cc] = p.y;
            }
            float sA[CH], sB[CH];
#pragma unroll
            for (int cc = 0; cc < CH; cc++) {
                float up = __shfl_up_sync(0xffffffffu, hB, 1);  // chain: hB(cc-1)
                float zA = fmaf(k0_up, up, fmaf(k1, hA, qA[cc]));
                float zB = fmaf(k0, hA, fmaf(k1, hB, pB[cc]));  // old hA, hB
                hA = htanh(zA);
                hB = htanh(zB);
                sA[cc] = hA; sB[cc] = hB;
            }
            const int ab = n & 1;
#pragma unroll
            for (int cc = 0; cc < CH; cc++) {
                float2 v = make_float2(sA[cc], sB[cc]);
                *(float2*)&s_act[ab][cc][(2 * lane) ^ (4 * (cc & 7))] = v;
            }
            // lane 31 (row base+63 = block's last row) publishes boundary now.
            if (lane == 31) {
                float4* dst = (float4*)(brow + n * CH);
                dst[0] = make_float4(sB[0],  sB[1],  sB[2],  sB[3]);
                dst[1] = make_float4(sB[4],  sB[5],  sB[6],  sB[7]);
                dst[2] = make_float4(sB[8],  sB[9],  sB[10], sB[11]);
                dst[3] = make_float4(sB[12], sB[13], sB[14], sB[15]);
                rel_store(&g_progress[b][0], (n + 1) * CH);     // release: orders STGs
            }
        }
        __syncthreads();                  // final: hand last act tile to warp 1
    } else if (wid == 1) {
        // ================= image / activation warp =================
        const int fr = lane >> 3;         // 0..3 : row sub-index within group
        const int fc = lane & 7;          // 0..7 : column sub-index
        int Bidx[16], off[16], swz[16];   // chunk m: global addr = Bidx + 16*m (+8)
#pragma unroll
        for (int it = 0; it < 16; it++) {
            int gr   = base + it * 4 + fr;
            off[it]  = fc - gr;                    // global col = a + off (+8)
            Bidx[it] = gr * (W - 1) + fc;          // unskew/img addr = Bidx + a (+8)
            swz[it]  = (it * 4 + fr) ^ (4 * fc);   // swizzled row position
        }

        // prologue: img chunks 0,1 -> smem (pre-affine); chunk 2 -> regs (raw)
        float rg[32];
#pragma unroll
        for (int it = 0; it < 16; it++) {
            int o = off[it];
            { int c = o;      s_img[0][fc][swz[it]]   = ((unsigned)c < W) ? fmaf(w, img[Bidx[it]],      cb) : cb; }
            { int c = o + 8;  s_img[0][fc+8][swz[it]] = ((unsigned)c < W) ? fmaf(w, img[Bidx[it] + 8],  cb) : cb; }
            { int c = o + 16; s_img[1][fc][swz[it]]   = ((unsigned)c < W) ? fmaf(w, img[Bidx[it] + 16], cb) : cb; }
            { int c = o + 24; s_img[1][fc+8][swz[it]] = ((unsigned)c < W) ? fmaf(w, img[Bidx[it] + 24], cb) : cb; }
            { int c = o + 32; rg[2*it]                = ((unsigned)c < W) ? img[Bidx[it] + 32] : 0.f; }
            { int c = o + 40; rg[2*it+1]              = ((unsigned)c < W) ? img[Bidx[it] + 40] : 0.f; }
        }

        for (int n = 0; n < NCHUNK; n++) {
            __syncthreads();
            const int m2 = n + 2, m3 = n + 3;
            // publish staged img chunk n+2 into smem (apply affine here)
            if (m2 < NCHUNK) {
                const int bi = m2 % 3;
#pragma unroll
                for (int it = 0; it < 16; it++) {
                    s_img[bi][fc][swz[it]]   = fmaf(w, rg[2*it],   cb);
                    s_img[bi][fc+8][swz[it]] = fmaf(w, rg[2*it+1], cb);
                }
            }
            // issue img loads for chunk n+3 (one full window of latency slack)
            if (m3 < NCHUNK) {
                const int a = m3 * CH;
#pragma unroll
                for (int it = 0; it < 16; it++) {
                    int c0 = a + off[it];
                    rg[2*it]   = ((unsigned)c0 < W)     ? img[Bidx[it] + a]     : 0.f;
                    rg[2*it+1] = ((unsigned)(c0+8) < W) ? img[Bidx[it] + a + 8] : 0.f;
                }
            }
            // flush activation tile of chunk n-1 (coalesced)
            if (n >= 1) {
                const int fb = (n - 1) & 1;
                const int a  = (n - 1) * CH;
#pragma unroll
                for (int it = 0; it < 16; it++) {
                    int c0 = a + off[it];
                    float v0 = s_act[fb][fc][swz[it]];
                    float v1 = s_act[fb][fc+8][swz[it]];
                    if ((unsigned)c0 < W)     g_unskew[Bidx[it] + a]     = v0;
                    if ((unsigned)(c0+8) < W) g_unskew[Bidx[it] + a + 8] = v1;
                }
            }
        }
        __syncthreads();
        // epilogue: flush final activation chunk
        {
            const int fb = (NCHUNK - 1) & 1;
            const int a  = (NCHUNK - 1) * CH;
#pragma unroll
            for (int it = 0; it < 16; it++) {
                int c0 = a + off[it];
                float v0 = s_act[fb][fc][swz[it]];
                float v1 = s_act[fb][fc+8][swz[it]];
                if ((unsigned)c0 < W)     g_unskew[Bidx[it] + a]     = v0;
                if ((unsigned)(c0+8) < W) g_unskew[Bidx[it] + a + 8] = v1;
            }
        }
    } else {
        // ================= boundary-sync warp =================
        const float* ub     = (b > 0) ? g_bound[b - 1] : g_bound[0];
        const int*   upflag = (b > 0) ? &g_progress[b - 1][0] : &g_progress[0][0];
        int kn = 0;

        // prologue: chunks 0,1 (zeros above the image for block 0)
        if (lane < CH) { s_bnd[0][lane] = 0.f; s_bnd[1][lane] = 0.f; s_bnd[2][lane] = 0.f; }
        if (b > 0) {
            while (kn < CH - 1) kn = acq_load(upflag);
            if (lane > 0 && lane < CH) s_bnd[0][lane] = ldcg(ub + lane - 1);
            while (kn < 2 * CH - 1) kn = acq_load(upflag);
            if (lane < CH) s_bnd[1][lane] = ldcg(ub + CH - 1 + lane);
        }

        for (int n = 0; n < NCHUNK; n++) {
            __syncthreads();
            // fetch boundary chunk n+2 (distance-2: poll + L2 latency fully
            // overlapped with warps 0/1; consumed 2 barriers later)
            const int m = n + 2;
            if (b > 0 && m < NCHUNK) {
                const int need = (m + 1) * CH - 1;
                while (kn < need) kn = acq_load(upflag);
                if (lane < CH) s_bnd[m % 3][lane] = ldcg(ub + m * CH - 1 + lane);
            }
        }
        __syncthreads();
    }
}

// out[f][o] = dot(unskew_flat[f], fc_w[o]) + fc_b[o]; 10 warps, one per output
__global__ void fc_kernel(const float* __restrict__ fc_w, const float* __restrict__ fc_b,
                          float* __restrict__ out) {
    __shared__ float4 sact[FC_IN / 4];
    const int f = blockIdx.x;
    const float4* src = (const float4*)(g_unskew + (size_t)f * FC_IN);
    if (threadIdx.x < FC_IN / 4) sact[threadIdx.x] = src[threadIdx.x];
    __syncthreads();
    const int wid  = threadIdx.x >> 5;
    const int lane = threadIdx.x & 31;
    if (wid < FC_OUT) {
        const float4* wr = (const float4*)(fc_w + (size_t)wid * FC_IN);
        float acc = 0.0f;
#pragma unroll
        for (int i = 0; i < 8; i++) {
            float4 a  = sact[lane + i * 32];
            float4 wv = wr[lane + i * 32];
            acc = fmaf(a.x, wv.x, acc);
            acc = fmaf(a.y, wv.y, acc);
            acc = fmaf(a.z, wv.z, acc);
            acc = fmaf(a.w, wv.w, acc);
        }
#pragma unroll
        for (int s = 16; s > 0; s >>= 1) acc += __shfl_down_sync(0xffffffffu, acc, s);
        if (lane == 0) out[f * FC_OUT + wid] = acc + fc_b[wid];
    }
}

// Clears progress flags AFTER each invocation so the next replay starts clean.
// (Globals are zero-initialized, so the very first call is also clean.)
__global__ void reset_kernel() {
    ((int*)g_progress)[threadIdx.x] = 0;
}

extern "C" void kernel_launch(void* const* d_in, const int* in_sizes, int n_in,
                              void* d_out, int out_size) {
    const float* x       = (const float*)d_in[0];
    const float* w_in    = (const float*)d_in[1];
    const float* b_in    = (const float*)d_in[2];
    const float* w_state = (const float*)d_in[3];
    const float* b_state = (const float*)d_in[4];
    const float* fc_w    = (const float*)d_in[5];
    const float* fc_b    = (const float*)d_in[6];
    (void)in_sizes; (void)n_in; (void)out_size;

    scan_kernel<<<NBLK, 96>>>(x, w_in, b_in, w_state, b_state);
    fc_kernel<<<NFLAT, 320>>>(fc_w, fc_b, (float*)d_out);
    reset_kernel<<<1, NBLK * 32>>>();   // flags clean for the next graph replay
}